// round 2
// baseline (speedup 1.0000x reference)
#include <cuda_runtime.h>
#include <cuda_fp16.h>

#define N_NODES 50000
#define N_EDGES 800000
#define D_FEAT  128

// ---- device-global scratch (no runtime allocation allowed) ----
__device__ int g_row_ptr[N_NODES + 1];
// x quantized to fp16: 50000 * 128 halves = 12.8 MB, stored as uint2 (4 halves each)
__device__ uint2 g_x_half[(size_t)N_NODES * D_FEAT / 4];

// ---- prologue 1: convert x (f32) -> fp16 packed ----
__global__ __launch_bounds__(256)
void convert_x_kernel(const float* __restrict__ x) {
    int i = blockIdx.x * blockDim.x + threadIdx.x;   // one float4 -> one uint2
    const int total = N_NODES * D_FEAT / 4;
    if (i >= total) return;
    float4 a = ((const float4*)x)[i];
    __half2 lo = __floats2half2_rn(a.x, a.y);
    __half2 hi = __floats2half2_rn(a.z, a.w);
    uint2 out;
    out.x = *(unsigned int*)&lo;
    out.y = *(unsigned int*)&hi;
    g_x_half[i] = out;
}

// ---- prologue 2: CSR row_ptr from sorted COO rows (edge-parallel) ----
__global__ void build_row_ptr_kernel(const int* __restrict__ rows) {
    int e = blockIdx.x * blockDim.x + threadIdx.x;
    if (e >= N_EDGES) return;
    int r = rows[e];
    int rprev = (e == 0) ? -1 : rows[e - 1];
    for (int q = rprev + 1; q <= r; q++) g_row_ptr[q] = e;
    if (e == N_EDGES - 1) {
        for (int q = r + 1; q <= N_NODES; q++) g_row_ptr[q] = N_EDGES;
    }
}

// ---- main: one warp per row, fp16 gather (256 B/edge), fp32 accumulate ----
// Lane l owns features [4l, 4l+4): loads one uint2 (4 halves) per edge,
// stores one float4 at the end. Atomic-free (rows sorted -> contiguous segs).
__global__ __launch_bounds__(256)
void spmm_coo_kernel(const float* __restrict__ vals,
                     const int* __restrict__ cols,
                     float* __restrict__ out) {
    int warp = (blockIdx.x * blockDim.x + threadIdx.x) >> 5;
    int lane = threadIdx.x & 31;
    if (warp >= N_NODES) return;

    int start = g_row_ptr[warp];
    int end   = g_row_ptr[warp + 1];

    float4 acc = make_float4(0.f, 0.f, 0.f, 0.f);

    for (int base = start; base < end; base += 32) {
        int n = end - base;
        if (n > 32) n = 32;

        // Cooperative, coalesced load of this chunk's edge metadata.
        int   c = 0;
        float v = 0.f;
        if (lane < n) {
            c = cols[base + lane];
            v = vals[base + lane];
        }

        // Broadcast each edge; gathers independent of acc -> MLP.
        #pragma unroll 4
        for (int j = 0; j < n; j++) {
            int   cj = __shfl_sync(0xffffffffu, c, j);
            float vj = __shfl_sync(0xffffffffu, v, j);
            uint2 h  = g_x_half[(size_t)cj * (D_FEAT / 4) + lane];
            __half2 h0 = *(__half2*)&h.x;
            __half2 h1 = *(__half2*)&h.y;
            float2 f0 = __half22float2(h0);
            float2 f1 = __half22float2(h1);
            acc.x += vj * f0.x;
            acc.y += vj * f0.y;
            acc.z += vj * f1.x;
            acc.w += vj * f1.y;
        }
    }

    ((float4*)out)[(size_t)warp * (D_FEAT / 4) + lane] = acc;
}

extern "C" void kernel_launch(void* const* d_in, const int* in_sizes, int n_in,
                              void* d_out, int out_size) {
    const float* x    = (const float*)d_in[0];
    const float* vals = (const float*)d_in[1];
    const int*   rows = (const int*)d_in[2];
    const int*   cols = (const int*)d_in[3];
    float*       out  = (float*)d_out;

    (void)in_sizes; (void)n_in; (void)out_size;

    // 1) x -> fp16 (halves gather traffic through L2)
    {
        int total   = N_NODES * D_FEAT / 4;
        int threads = 256;
        int blocks  = (total + threads - 1) / threads;
        convert_x_kernel<<<blocks, threads>>>(x);
    }

    // 2) CSR row_ptr from sorted COO rows
    {
        int threads = 256;
        int blocks  = (N_EDGES + threads - 1) / threads;
        build_row_ptr_kernel<<<blocks, threads>>>(rows);
    }

    // 3) Warp-per-row SpMM, fp16 gather, fp32 accumulate, atomic-free
    {
        int threads = 256;  // 8 warps/block
        int blocks  = (N_NODES * 32 + threads - 1) / threads;
        spmm_coo_kernel<<<blocks, threads>>>(vals, cols, out);
    }
}